// round 5
// baseline (speedup 1.0000x reference)
#include <cuda_runtime.h>
#include <math.h>

// Problem constants (fixed shapes)
#define B      64
#define EMB    1024
#define WID    64
#define MODES  16
#define LSEQ   8192
#define LOUT   8190       // LSEQ - PADDING(2)
#define NH     128        // hidden width of MLP
#define DECM   2048       // WID*MODES*2
#define KS     32         // split-K slices in kernel 1
#define KSL    32         // k per slice (EMB/KS)

typedef unsigned long long u64;

// Scratch (allocation-free rule: __device__ globals)
__device__ float  g_Hp[KS][B][DECM];      // split-K partials (16 MB, L2-resident)
__device__ float  g_H[B][DECM];           // reduced H
__device__ float4 g_R[B * NH * 8];        // interleaved (P,Q) coeffs [B][128 j][16 modes *2]

// ---- packed f32x2 helpers (Blackwell FFMA2) --------------------------------
__device__ __forceinline__ u64 pk2(float lo, float hi) {
    u64 r; asm("mov.b64 %0, {%1,%2};" : "=l"(r) : "f"(lo), "f"(hi)); return r;
}
__device__ __forceinline__ void upk2(u64 v, float& lo, float& hi) {
    asm("mov.b64 {%0,%1}, %2;" : "=f"(lo), "=f"(hi) : "l"(v));
}
__device__ __forceinline__ u64 ffma2(u64 a, u64 b, u64 c) {
    u64 d; asm("fma.rn.f32x2 %0, %1, %2, %3;" : "=l"(d) : "l"(a), "l"(b), "l"(c)); return d;
}
__device__ __forceinline__ u64 fmul2(u64 a, u64 b) {
    u64 d; asm("mul.rn.f32x2 %0, %1, %2;" : "=l"(d) : "l"(a), "l"(b)); return d;
}
__device__ __forceinline__ float rcp_fast(float x) {
    float r; asm("rcp.approx.f32 %0, %1;" : "=f"(r) : "f"(x)); return r;
}
__device__ __forceinline__ float ex2_fast(float x) {
    float r; asm("ex2.approx.f32 %0, %1;" : "=f"(r) : "f"(x)); return r;
}

// ---------------------------------------------------------------------------
// Kernel 1: split-K GEMM  Hp[ks] = token[:, slice] @ w_dec[slice, :]
// ---------------------------------------------------------------------------
__global__ void __launch_bounds__(256) fno_decode_gemm(
    const float* __restrict__ token,   // [B][EMB]
    const float* __restrict__ wdec)    // [EMB][DECM]
{
    __shared__ float4 Ts4[B][KSL / 4];   // 8 KB token tile

    const int n     = blockIdx.x * 128 + (threadIdx.x & 127);
    const int mhalf = threadIdx.x >> 7;
    const int k0    = blockIdx.y * KSL;

    const float4* tok4 = (const float4*)token;
    for (int i = threadIdx.x; i < B * (KSL / 4); i += 256) {
        int m = i >> 3, q = i & 7;
        Ts4[m][q] = tok4[m * (EMB / 4) + (k0 >> 2) + q];
    }
    __syncthreads();

    float acc[32];
#pragma unroll
    for (int mm = 0; mm < 32; mm++) acc[mm] = 0.f;

#pragma unroll
    for (int kk4 = 0; kk4 < KSL / 4; kk4++) {
        const int kg = k0 + kk4 * 4;
        const float w0 = wdec[(kg + 0) * DECM + n];
        const float w1_ = wdec[(kg + 1) * DECM + n];
        const float w2_ = wdec[(kg + 2) * DECM + n];
        const float w3_ = wdec[(kg + 3) * DECM + n];
#pragma unroll
        for (int mm = 0; mm < 32; mm++) {
            float4 t = Ts4[mhalf * 32 + mm][kk4];   // warp-broadcast LDS.128
            float a = acc[mm];
            a = fmaf(t.x, w0, a);
            a = fmaf(t.y, w1_, a);
            a = fmaf(t.z, w2_, a);
            a = fmaf(t.w, w3_, a);
            acc[mm] = a;
        }
    }
#pragma unroll
    for (int mm = 0; mm < 32; mm++)
        g_Hp[blockIdx.y][mhalf * 32 + mm][n] = acc[mm];
}

// ---------------------------------------------------------------------------
// Kernel 1b: reduce split-K partials + bias -> g_H
// ---------------------------------------------------------------------------
__global__ void __launch_bounds__(256) fno_reduce(
    const float* __restrict__ bdec)
{
    const int base = (blockIdx.x * 256 + threadIdx.x) * 2;
    const int b0 = base / DECM, i0 = base % DECM;
    float h0 = bdec[i0], h1 = bdec[i0 + 1];
#pragma unroll
    for (int ks = 0; ks < KS; ks++) {
        h0 += g_Hp[ks][b0][i0];
        h1 += g_Hp[ks][b0][i0 + 1];
    }
    g_H[b0][i0]     = h0;
    g_H[b0][i0 + 1] = h1;
}

// ---------------------------------------------------------------------------
// Kernel 2: build spectral->hidden coefficients
// ---------------------------------------------------------------------------
__global__ void __launch_bounds__(128) fno_build_R(
    const float* __restrict__ w1)      // [WID][NH]
{
    __shared__ float Hs[DECM];         // 8 KB  [w][k][2]
    __shared__ float w1s[WID][16];     // 4 KB
    const int b  = blockIdx.x;
    const int j0 = blockIdx.y * 16;

    for (int i = threadIdx.x; i < DECM; i += 128) Hs[i] = g_H[b][i];
    for (int i = threadIdx.x; i < WID * 16; i += 128) {
        int w = i >> 4, jj = i & 15;
        w1s[w][jj] = w1[w * NH + j0 + jj];
    }
    __syncthreads();

    const float inv = 1.0f / (float)LSEQ;
    float* Rf = (float*)g_R;

#pragma unroll
    for (int q = 0; q < 2; q++) {
        int c  = threadIdx.x + q * 128;
        int jj = c >> 4;
        int k  = c & 15;
        float P = 0.f, Q = 0.f;
#pragma unroll 8
        for (int w = 0; w < WID; w++) {
            float a = w1s[w][jj];
            P = fmaf(a, Hs[w * 32 + 2 * k],     P);
            Q = fmaf(a, Hs[w * 32 + 2 * k + 1], Q);
        }
        float sA = (k == 0) ? inv : 2.0f * inv;
        float sB = (k == 0) ? 0.f : -2.0f * inv;
        int j = j0 + jj;
        Rf[(b * NH + j) * 32 + 2 * k]     = sA * P;
        Rf[(b * NH + j) * 32 + 2 * k + 1] = sB * Q;
    }
}

// ---------------------------------------------------------------------------
// Packed gelu pair: gp = gelu((hp.lo, hp.hi)) via branchless A&S 7.1.26 erf.
//   z = h/sqrt(2);  R = t*poly5(t)*exp(-z^2), t = 1/(1+p|z|)
//   gelu(h) = relu(h) - 0.5*|h|*R     (exact for both signs)
// ---------------------------------------------------------------------------
__device__ __forceinline__ u64 gelu2(u64 hp, float h_lo, float h_hi)
{
    const u64 ABSM = 0x7FFFFFFF7FFFFFFFULL;
    const u64 SGNM = 0x8000000080000000ULL;
    const u64 C07  = 0x3F3504F33F3504F3ULL;  // 0.70710678f x2
    const u64 KP   = 0x3EA7BA0A3EA7BA0AULL;  // 0.3275911f x2
    const u64 ONE2 = 0x3F8000003F800000ULL;  // 1.0f x2
    const u64 NL2E = 0xBFB8AA3BBFB8AA3BULL;  // -1.4426950408889634f x2
    const u64 A5   = 0x3F87DC0A3F87DC0AULL;  // 1.061405429f
    const u64 A4   = 0xBFBA00E3BFBA00E3ULL;  // -1.453152027f
    const u64 A3   = 0x3FB5F0BC3FB5F0BCULL;  // 1.421413741f
    const u64 A2   = 0xBE919B27BE919B27ULL;  // -0.284496736f
    const u64 A1   = 0x3E8279063E827906ULL;  // 0.254829592f

    u64 zp  = fmul2(hp, C07);
    u64 azp = zp & ABSM;
    u64 dp  = ffma2(azp, KP, ONE2);
    float d0, d1; upk2(dp, d0, d1);
    u64 tp  = pk2(rcp_fast(d0), rcp_fast(d1));
    u64 zz  = fmul2(zp, zp);
    u64 ea  = fmul2(zz, NL2E);
    float e0, e1; upk2(ea, e0, e1);
    u64 ep  = pk2(ex2_fast(e0), ex2_fast(e1));
    u64 pp  = ffma2(tp, A5, A4);
    pp = ffma2(tp, pp, A3);
    pp = ffma2(tp, pp, A2);
    pp = ffma2(tp, pp, A1);
    u64 Rp  = fmul2(fmul2(tp, pp), ep);
    u64 Rn  = Rp ^ SGNM;                      // -R
    u64 hbp = fmul2(azp, C07);                // 0.5*|h| = |z|*0.7071
    u64 relup = pk2(fmaxf(h_lo, 0.f), fmaxf(h_hi, 0.f));
    return ffma2(hbp, Rn, relup);             // relu(h) - 0.5|h|R
}

// ---------------------------------------------------------------------------
// Kernel 3 (hot): FOUR positions per thread via trig symmetry + packed gelu.
// grid (17 chunks, 64 b), 128 threads; t in [0,2048].
// ---------------------------------------------------------------------------
__global__ void __launch_bounds__(128) fno_main(
    const float* __restrict__ b1,
    const float* __restrict__ w2,
    const float* __restrict__ b2,
    float* __restrict__ out)
{
    __shared__ float4 Rs[NH * 8];      // 16 KB, (P,Q) pairs per mode
    __shared__ float  b1s[NH], w2s[NH];

    const int b = blockIdx.y;
    const float4* Rg = g_R + b * NH * 8;
    for (int i = threadIdx.x; i < NH * 8; i += 128) Rs[i] = Rg[i];
    b1s[threadIdx.x] = b1[threadIdx.x];
    w2s[threadIdx.x] = w2[threadIdx.x];
    __syncthreads();

    const int t = blockIdx.x * 128 + threadIdx.x;
    if (t > 2048) return;

    // trig via one sincos + Chebyshev recurrence, packed (c,s) per mode
    float c[MODES], s[MODES];
    float ang = (float)t * 7.6699039394282067e-4f;  // 2*pi/8192
    float s1, c1;
    sincosf(ang, &s1, &c1);
    c[0] = 1.f; s[0] = 0.f;
    c[1] = c1;  s[1] = s1;
    const float t2 = 2.f * c1;
#pragma unroll
    for (int k = 2; k < MODES; k++) {
        c[k] = fmaf(t2, c[k - 1], -c[k - 2]);
        s[k] = fmaf(t2, s[k - 1], -s[k - 2]);
    }
    u64 cs[MODES];
#pragma unroll
    for (int k = 0; k < MODES; k++) cs[k] = pk2(c[k], s[k]);

    float acc1 = 0.f, acc2 = 0.f, acc3 = 0.f, acc4 = 0.f;
#pragma unroll 2
    for (int j = 0; j < NH; j++) {
        const ulonglong2* rj = (const ulonglong2*)(Rs + j * 8);
        ulonglong2 r0 = rj[0];                    // ld.shared.v2.u64 (broadcast)
        u64 e = fmul2(r0.x, cs[0]);               // even modes: (Sum P*c, Sum Q*s)
        u64 o = fmul2(r0.y, cs[1]);               // odd modes
#pragma unroll
        for (int kp = 1; kp < 8; kp++) {
            ulonglong2 rr = rj[kp];
            e = ffma2(rr.x, cs[2 * kp],     e);
            o = ffma2(rr.y, cs[2 * kp + 1], o);
        }
        float ePc, eQs, oPc, oQs;
        upk2(e, ePc, eQs);
        upk2(o, oPc, oQs);
        const float bb = b1s[j];
        float S1 = ePc + eQs, S2 = oPc + oQs;
        float S3 = ePc - eQs, S4 = oPc - oQs;
        float hA = bb + S1;
        float hB = bb + S3;
        float h1 = hA + S2;   // pos t
        float h3 = hA - S2;   // pos 4096+t
        float h4 = hB + S4;   // pos 8192-t
        float h2 = hB - S4;   // pos 4096-t

        u64 g13 = gelu2(pk2(h1, h3), h1, h3);
        u64 g24 = gelu2(pk2(h2, h4), h2, h4);
        float g1, g3, g2, g4;
        upk2(g13, g1, g3);
        upk2(g24, g2, g4);
        const float wj = w2s[j];
        acc1 = fmaf(g1, wj, acc1);
        acc2 = fmaf(g2, wj, acc2);
        acc3 = fmaf(g3, wj, acc3);
        acc4 = fmaf(g4, wj, acc4);
    }
    const float bias2 = b2[0];
    float* ob = out + b * LOUT;
    ob[t] = acc1 + bias2;                                   // 0..2048
    if (t > 0 && t < 2048) ob[4096 - t] = acc2 + bias2;     // 2049..4095
    ob[4096 + t] = acc3 + bias2;                            // 4096..6144
    if (t > 2 && t < 2048) ob[8192 - t] = acc4 + bias2;     // 6145..8189
}

// ---------------------------------------------------------------------------
extern "C" void kernel_launch(void* const* d_in, const int* in_sizes, int n_in,
                              void* d_out, int out_size)
{
    // inputs: token, [x_len], w_dec, b_dec, w1, b1, w2, b2
    const float* token = (const float*)d_in[0];
    int wi = (in_sizes[1] < 100) ? 2 : 1;   // skip x_len scalar if present
    const float* wdec = (const float*)d_in[wi + 0];
    const float* bdec = (const float*)d_in[wi + 1];
    const float* w1   = (const float*)d_in[wi + 2];
    const float* b1   = (const float*)d_in[wi + 3];
    const float* w2   = (const float*)d_in[wi + 4];
    const float* b2   = (const float*)d_in[wi + 5];
    float* out = (float*)d_out;

    fno_decode_gemm<<<dim3(DECM / 128, KS), 256>>>(token, wdec);
    fno_reduce<<<B * DECM / 512, 256>>>(bdec);
    fno_build_R<<<dim3(B, 8), 128>>>(w1);
    fno_main<<<dim3(17, B), 128>>>(b1, w2, b2, out);
}

// round 6
// speedup vs baseline: 1.6059x; 1.6059x over previous
#include <cuda_runtime.h>
#include <math.h>

// Problem constants (fixed shapes)
#define B      64
#define EMB    1024
#define WID    64
#define MODES  16
#define LSEQ   8192
#define LOUT   8190       // LSEQ - PADDING(2)
#define NH     128        // hidden width of MLP
#define DECM   2048       // WID*MODES*2
#define KS     32         // split-K slices in kernel 1
#define KSL    32         // k per slice (EMB/KS)

typedef unsigned long long u64;

// Scratch (allocation-free rule: __device__ globals)
__device__ float  g_Hp[KS][B][DECM];      // split-K partials (16 MB, L2-resident)
__device__ float  g_H[B][DECM];           // reduced H
__device__ float4 g_R[B * NH * 8];        // interleaved (P,Q) coeffs [B][128 j][16 modes *2]

// ---- packed f32x2 helpers (Blackwell FFMA2) -- used ONLY in the mode-sum ---
__device__ __forceinline__ u64 pk2(float lo, float hi) {
    u64 r; asm("mov.b64 %0, {%1,%2};" : "=l"(r) : "f"(lo), "f"(hi)); return r;
}
__device__ __forceinline__ void upk2(u64 v, float& lo, float& hi) {
    asm("mov.b64 {%0,%1}, %2;" : "=f"(lo), "=f"(hi) : "l"(v));
}
__device__ __forceinline__ u64 ffma2(u64 a, u64 b, u64 c) {
    u64 d; asm("fma.rn.f32x2 %0, %1, %2, %3;" : "=l"(d) : "l"(a), "l"(b), "l"(c)); return d;
}
__device__ __forceinline__ u64 fmul2(u64 a, u64 b) {
    u64 d; asm("mul.rn.f32x2 %0, %1, %2;" : "=l"(d) : "l"(a), "l"(b)); return d;
}
__device__ __forceinline__ float rcp_fast(float x) {
    float r; asm("rcp.approx.f32 %0, %1;" : "=f"(r) : "f"(x)); return r;
}
__device__ __forceinline__ float ex2_fast(float x) {
    float r; asm("ex2.approx.f32 %0, %1;" : "=f"(r) : "f"(x)); return r;
}

// ---------------------------------------------------------------------------
// Scalar branchless gelu via A&S 7.1.26 erf (|eps| ~ 1.5e-7):
//   z = h/sqrt(2); t = 1/(1+p|z|); R = t*poly5(t)*exp(-z^2)
//   gelu(h) = relu(h) - 0.5*|h|*R      (exact identity for both signs)
// 13 issue slots + 2 MUFU, zero pack/unpack glue.
// ---------------------------------------------------------------------------
__device__ __forceinline__ float gelu1(float h)
{
    const float C07 = 0.70710678118654752f;
    float z  = h * C07;
    float az = fabsf(z);
    float d  = fmaf(az, 0.3275911f, 1.0f);
    float t  = rcp_fast(d);
    float ee = ex2_fast(z * z * -1.4426950408889634f);
    float p  = fmaf(t, 1.061405429f, -1.453152027f);
    p = fmaf(t, p, 1.421413741f);
    p = fmaf(t, p, -0.284496736f);
    p = fmaf(t, p, 0.254829592f);
    float R  = t * p * ee;
    float hb = az * C07;                  // 0.5*|h|
    return fmaf(-hb, R, fmaxf(h, 0.f));
}

// ---------------------------------------------------------------------------
// Kernel 1: split-K GEMM  Hp[ks] = token[:, slice] @ w_dec[slice, :]
// ---------------------------------------------------------------------------
__global__ void __launch_bounds__(256) fno_decode_gemm(
    const float* __restrict__ token,   // [B][EMB]
    const float* __restrict__ wdec)    // [EMB][DECM]
{
    __shared__ float4 Ts4[B][KSL / 4];   // 8 KB token tile

    const int n     = blockIdx.x * 128 + (threadIdx.x & 127);
    const int mhalf = threadIdx.x >> 7;
    const int k0    = blockIdx.y * KSL;

    const float4* tok4 = (const float4*)token;
    for (int i = threadIdx.x; i < B * (KSL / 4); i += 256) {
        int m = i >> 3, q = i & 7;
        Ts4[m][q] = tok4[m * (EMB / 4) + (k0 >> 2) + q];
    }
    __syncthreads();

    float acc[32];
#pragma unroll
    for (int mm = 0; mm < 32; mm++) acc[mm] = 0.f;

#pragma unroll
    for (int kk4 = 0; kk4 < KSL / 4; kk4++) {
        const int kg = k0 + kk4 * 4;
        const float w0 = wdec[(kg + 0) * DECM + n];
        const float w1_ = wdec[(kg + 1) * DECM + n];
        const float w2_ = wdec[(kg + 2) * DECM + n];
        const float w3_ = wdec[(kg + 3) * DECM + n];
#pragma unroll
        for (int mm = 0; mm < 32; mm++) {
            float4 t = Ts4[mhalf * 32 + mm][kk4];   // warp-broadcast LDS.128
            float a = acc[mm];
            a = fmaf(t.x, w0, a);
            a = fmaf(t.y, w1_, a);
            a = fmaf(t.z, w2_, a);
            a = fmaf(t.w, w3_, a);
            acc[mm] = a;
        }
    }
#pragma unroll
    for (int mm = 0; mm < 32; mm++)
        g_Hp[blockIdx.y][mhalf * 32 + mm][n] = acc[mm];
}

// ---------------------------------------------------------------------------
// Kernel 1b: reduce split-K partials + bias -> g_H
// ---------------------------------------------------------------------------
__global__ void __launch_bounds__(256) fno_reduce(
    const float* __restrict__ bdec)
{
    const int base = (blockIdx.x * 256 + threadIdx.x) * 2;
    const int b0 = base / DECM, i0 = base % DECM;
    float h0 = bdec[i0], h1 = bdec[i0 + 1];
#pragma unroll
    for (int ks = 0; ks < KS; ks++) {
        h0 += g_Hp[ks][b0][i0];
        h1 += g_Hp[ks][b0][i0 + 1];
    }
    g_H[b0][i0]     = h0;
    g_H[b0][i0 + 1] = h1;
}

// ---------------------------------------------------------------------------
// Kernel 2: build spectral->hidden coefficients
// ---------------------------------------------------------------------------
__global__ void __launch_bounds__(128) fno_build_R(
    const float* __restrict__ w1)      // [WID][NH]
{
    __shared__ float Hs[DECM];         // 8 KB  [w][k][2]
    __shared__ float w1s[WID][16];     // 4 KB
    const int b  = blockIdx.x;
    const int j0 = blockIdx.y * 16;

    for (int i = threadIdx.x; i < DECM; i += 128) Hs[i] = g_H[b][i];
    for (int i = threadIdx.x; i < WID * 16; i += 128) {
        int w = i >> 4, jj = i & 15;
        w1s[w][jj] = w1[w * NH + j0 + jj];
    }
    __syncthreads();

    const float inv = 1.0f / (float)LSEQ;
    float* Rf = (float*)g_R;

#pragma unroll
    for (int q = 0; q < 2; q++) {
        int c  = threadIdx.x + q * 128;
        int jj = c >> 4;
        int k  = c & 15;
        float P = 0.f, Q = 0.f;
#pragma unroll 8
        for (int w = 0; w < WID; w++) {
            float a = w1s[w][jj];
            P = fmaf(a, Hs[w * 32 + 2 * k],     P);
            Q = fmaf(a, Hs[w * 32 + 2 * k + 1], Q);
        }
        float sA = (k == 0) ? inv : 2.0f * inv;
        float sB = (k == 0) ? 0.f : -2.0f * inv;
        int j = j0 + jj;
        Rf[(b * NH + j) * 32 + 2 * k]     = sA * P;
        Rf[(b * NH + j) * 32 + 2 * k + 1] = sB * Q;
    }
}

// ---------------------------------------------------------------------------
// Kernel 3 (hot): FOUR positions per thread via trig symmetry.
//   t in [0,2048]; positions { t, 4096-t, 4096+t, 8192-t } share (c_k, s_k).
//   Packed FFMA2 mode-sum (even/odd k), scalar combine + scalar A&S gelu.
// grid (9 chunks, 64 b), 256 threads.
// ---------------------------------------------------------------------------
__global__ void __launch_bounds__(256) fno_main(
    const float* __restrict__ b1,
    const float* __restrict__ w2,
    const float* __restrict__ b2,
    float* __restrict__ out)
{
    __shared__ float4 Rs[NH * 8];      // 16 KB, (P,Q) pairs per mode
    __shared__ float  b1s[NH], w2s[NH];

    const int b = blockIdx.y;
    const float4* Rg = g_R + b * NH * 8;
    for (int i = threadIdx.x; i < NH * 8; i += 256) Rs[i] = Rg[i];
    if (threadIdx.x < NH) {
        b1s[threadIdx.x] = b1[threadIdx.x];
        w2s[threadIdx.x] = w2[threadIdx.x];
    }
    __syncthreads();

    const int t = blockIdx.x * 256 + threadIdx.x;
    if (t > 2048) return;

    // trig via one sincos + Chebyshev recurrence, packed (c,s) per mode
    float c[MODES], s[MODES];
    float ang = (float)t * 7.6699039394282067e-4f;  // 2*pi/8192
    float s1, c1;
    sincosf(ang, &s1, &c1);
    c[0] = 1.f; s[0] = 0.f;
    c[1] = c1;  s[1] = s1;
    const float t2 = 2.f * c1;
#pragma unroll
    for (int k = 2; k < MODES; k++) {
        c[k] = fmaf(t2, c[k - 1], -c[k - 2]);
        s[k] = fmaf(t2, s[k - 1], -s[k - 2]);
    }
    u64 cs[MODES];
#pragma unroll
    for (int k = 0; k < MODES; k++) cs[k] = pk2(c[k], s[k]);

    float acc1 = 0.f, acc2 = 0.f, acc3 = 0.f, acc4 = 0.f;
#pragma unroll 2
    for (int j = 0; j < NH; j++) {
        const ulonglong2* rj = (const ulonglong2*)(Rs + j * 8);
        ulonglong2 r0 = rj[0];                    // ld.shared.v2.u64 (broadcast)
        u64 e = fmul2(r0.x, cs[0]);               // even modes: (Sum P*c, Sum Q*s)
        u64 o = fmul2(r0.y, cs[1]);               // odd modes
#pragma unroll
        for (int kp = 1; kp < 8; kp++) {
            ulonglong2 rr = rj[kp];
            e = ffma2(rr.x, cs[2 * kp],     e);
            o = ffma2(rr.y, cs[2 * kp + 1], o);
        }
        float ePc, eQs, oPc, oQs;
        upk2(e, ePc, eQs);
        upk2(o, oPc, oQs);
        const float bb = b1s[j];
        float S1 = ePc + eQs, S2 = oPc + oQs;
        float S3 = ePc - eQs, S4 = oPc - oQs;
        float hA = bb + S1;
        float hB = bb + S3;
        float h1 = hA + S2;   // pos t
        float h3 = hA - S2;   // pos 4096+t
        float h4 = hB + S4;   // pos 8192-t
        float h2 = hB - S4;   // pos 4096-t
        float g1 = gelu1(h1);
        float g2 = gelu1(h2);
        float g3 = gelu1(h3);
        float g4 = gelu1(h4);
        const float wj = w2s[j];
        acc1 = fmaf(g1, wj, acc1);
        acc2 = fmaf(g2, wj, acc2);
        acc3 = fmaf(g3, wj, acc3);
        acc4 = fmaf(g4, wj, acc4);
    }
    const float bias2 = b2[0];
    float* ob = out + b * LOUT;
    ob[t] = acc1 + bias2;                                   // 0..2048
    if (t > 0 && t < 2048) ob[4096 - t] = acc2 + bias2;     // 2049..4095
    ob[4096 + t] = acc3 + bias2;                            // 4096..6144
    if (t > 2 && t < 2048) ob[8192 - t] = acc4 + bias2;     // 6145..8189
}

// ---------------------------------------------------------------------------
extern "C" void kernel_launch(void* const* d_in, const int* in_sizes, int n_in,
                              void* d_out, int out_size)
{
    // inputs: token, [x_len], w_dec, b_dec, w1, b1, w2, b2
    const float* token = (const float*)d_in[0];
    int wi = (in_sizes[1] < 100) ? 2 : 1;   // skip x_len scalar if present
    const float* wdec = (const float*)d_in[wi + 0];
    const float* bdec = (const float*)d_in[wi + 1];
    const float* w1   = (const float*)d_in[wi + 2];
    const float* b1   = (const float*)d_in[wi + 3];
    const float* w2   = (const float*)d_in[wi + 4];
    const float* b2   = (const float*)d_in[wi + 5];
    float* out = (float*)d_out;

    fno_decode_gemm<<<dim3(DECM / 128, KS), 256>>>(token, wdec);
    fno_reduce<<<B * DECM / 512, 256>>>(bdec);
    fno_build_R<<<dim3(B, 8), 128>>>(w1);
    fno_main<<<dim3(9, B), 256>>>(b1, w2, b2, out);
}

// round 7
// speedup vs baseline: 1.6758x; 1.0436x over previous
#include <cuda_runtime.h>
#include <math.h>

// Problem constants (fixed shapes)
#define B      64
#define EMB    1024
#define WID    64
#define MODES  16
#define LSEQ   8192
#define LOUT   8190       // LSEQ - PADDING(2)
#define NH     128        // hidden width of MLP
#define DECM   2048       // WID*MODES*2
#define KS     32         // split-K slices in kernel 1
#define KSL    32         // k per slice (EMB/KS)

typedef unsigned long long u64;

// Scratch (allocation-free rule: __device__ globals)
__device__ float  g_Hp[KS][B][DECM];      // split-K partials (16 MB, L2-resident)
__device__ float  g_H[B][DECM];           // reduced H
__device__ float4 g_R[B * NH * 8];        // interleaved (P,Q) coeffs [B][128 j][16 modes *2]

// ---- packed f32x2 helpers (Blackwell FFMA2) --------------------------------
__device__ __forceinline__ u64 pk2(float lo, float hi) {
    u64 r; asm("mov.b64 %0, {%1,%2};" : "=l"(r) : "f"(lo), "f"(hi)); return r;
}
__device__ __forceinline__ void upk2(u64 v, float& lo, float& hi) {
    asm("mov.b64 {%0,%1}, %2;" : "=f"(lo), "=f"(hi) : "l"(v));
}
// in-place FFMA2: "+l" keeps the accumulator in its register pair (no marshal MOVs)
__device__ __forceinline__ void ffma2i(u64& d, u64 a, u64 b) {
    asm("fma.rn.f32x2 %0, %1, %2, %0;" : "+l"(d) : "l"(a), "l"(b));
}
__device__ __forceinline__ float rcp_fast(float x) {
    float r; asm("rcp.approx.f32 %0, %1;" : "=f"(r) : "f"(x)); return r;
}
__device__ __forceinline__ float ex2_fast(float x) {
    float r; asm("ex2.approx.f32 %0, %1;" : "=f"(r) : "f"(x)); return r;
}

// ---------------------------------------------------------------------------
// Scalar branchless gelu via A&S 7.1.25 3-term erf (|eps| <= 2.5e-5):
//   z = h/sqrt(2); t = 1/(1+0.47047|z|); R = t(a1 + t(a2 + t a3)) e^{-z^2}
//   gelu(h) = relu(h) - 0.5*|h|*R
// ---------------------------------------------------------------------------
__device__ __forceinline__ float gelu1(float h)
{
    const float C07 = 0.70710678118654752f;
    float z  = h * C07;
    float az = fabsf(z);
    float d  = fmaf(az, 0.47047f, 1.0f);
    float t  = rcp_fast(d);
    float ee = ex2_fast(z * z * -1.4426950408889634f);
    float p  = fmaf(t, 0.7478556f, -0.0958798f);
    p = fmaf(t, p, 0.3480242f);
    float R  = t * p * ee;
    float hb = az * C07;                  // 0.5*|h|
    return fmaf(-hb, R, fmaxf(h, 0.f));
}

// ---------------------------------------------------------------------------
// Kernel 1: split-K GEMM with packed-k FFMA2.
//   Hp[ks] = token[:, slice] @ w_dec[slice, :]
// grid (16 n-tiles, 32 k-slices), 128 threads.
// Token tile pre-packed as float2 (row p, row p+32) per k; accumulators are
// u64 (partial_k_even, partial_k_odd)?? -> NO: acc[p] = (row p sum, row p+32 sum),
// multiplier w broadcast into both halves.
// ---------------------------------------------------------------------------
__global__ void __launch_bounds__(128) fno_decode_gemm(
    const float* __restrict__ token,   // [B][EMB]
    const float* __restrict__ wdec)    // [EMB][DECM]
{
    __shared__ float2 Ts2[32][KSL];    // 8 KB: [pair p][k] = (tok[p][k], tok[p+32][k])

    const int n  = blockIdx.x * 128 + threadIdx.x;
    const int k0 = blockIdx.y * KSL;

    // fill: 64 rows x KSL floats via float4 loads, scatter into pair halves
    const float4* tok4 = (const float4*)token;
    for (int i = threadIdx.x; i < 64 * (KSL / 4); i += 128) {
        int row = i / (KSL / 4), q = i % (KSL / 4);
        float4 v = tok4[row * (EMB / 4) + (k0 >> 2) + q];
        int p = row & 31, half = row >> 5;
        ((float*)&Ts2[p][q * 4 + 0])[half] = v.x;
        ((float*)&Ts2[p][q * 4 + 1])[half] = v.y;
        ((float*)&Ts2[p][q * 4 + 2])[half] = v.z;
        ((float*)&Ts2[p][q * 4 + 3])[half] = v.w;
    }
    __syncthreads();

    u64 acc[32];
#pragma unroll
    for (int p = 0; p < 32; p++) acc[p] = 0ULL;

#pragma unroll 1
    for (int kk = 0; kk < KSL; kk += 2) {
        const int kg = k0 + kk;
        float w0 = wdec[kg * DECM + n];
        float w1 = wdec[(kg + 1) * DECM + n];
        u64 wp0 = pk2(w0, w0);
        u64 wp1 = pk2(w1, w1);
#pragma unroll
        for (int p = 0; p < 32; p++) {
            ulonglong2 tt = *(const ulonglong2*)&Ts2[p][kk];  // broadcast LDS.128
            ffma2i(acc[p], tt.x, wp0);   // (row p)*w0, (row p+32)*w0
            ffma2i(acc[p], tt.y, wp1);
        }
    }
#pragma unroll
    for (int p = 0; p < 32; p++) {
        float lo, hi;
        upk2(acc[p], lo, hi);
        g_Hp[blockIdx.y][p][n]      = lo;
        g_Hp[blockIdx.y][p + 32][n] = hi;
    }
}

// ---------------------------------------------------------------------------
// Kernel 1b: reduce split-K partials + bias -> g_H
// ---------------------------------------------------------------------------
__global__ void __launch_bounds__(256) fno_reduce(
    const float* __restrict__ bdec)
{
    const int base = (blockIdx.x * 256 + threadIdx.x) * 2;
    const int b0 = base / DECM, i0 = base % DECM;
    float h0 = bdec[i0], h1 = bdec[i0 + 1];
#pragma unroll
    for (int ks = 0; ks < KS; ks++) {
        h0 += g_Hp[ks][b0][i0];
        h1 += g_Hp[ks][b0][i0 + 1];
    }
    g_H[b0][i0]     = h0;
    g_H[b0][i0 + 1] = h1;
}

// ---------------------------------------------------------------------------
// Kernel 2: build spectral->hidden coefficients
// ---------------------------------------------------------------------------
__global__ void __launch_bounds__(128) fno_build_R(
    const float* __restrict__ w1)      // [WID][NH]
{
    __shared__ float Hs[DECM];         // 8 KB  [w][k][2]
    __shared__ float w1s[WID][16];     // 4 KB
    const int b  = blockIdx.x;
    const int j0 = blockIdx.y * 16;

    for (int i = threadIdx.x; i < DECM; i += 128) Hs[i] = g_H[b][i];
    for (int i = threadIdx.x; i < WID * 16; i += 128) {
        int w = i >> 4, jj = i & 15;
        w1s[w][jj] = w1[w * NH + j0 + jj];
    }
    __syncthreads();

    const float inv = 1.0f / (float)LSEQ;
    float* Rf = (float*)g_R;

#pragma unroll
    for (int q = 0; q < 2; q++) {
        int c  = threadIdx.x + q * 128;
        int jj = c >> 4;
        int k  = c & 15;
        float P = 0.f, Q = 0.f;
#pragma unroll 8
        for (int w = 0; w < WID; w++) {
            float a = w1s[w][jj];
            P = fmaf(a, Hs[w * 32 + 2 * k],     P);
            Q = fmaf(a, Hs[w * 32 + 2 * k + 1], Q);
        }
        float sA = (k == 0) ? inv : 2.0f * inv;
        float sB = (k == 0) ? 0.f : -2.0f * inv;
        int j = j0 + jj;
        Rf[(b * NH + j) * 32 + 2 * k]     = sA * P;
        Rf[(b * NH + j) * 32 + 2 * k + 1] = sB * Q;
    }
}

// ---------------------------------------------------------------------------
// Kernel 3 (hot): FOUR positions per thread via trig symmetry.
//   t in [0,2048]; positions { t, 4096-t, 4096+t, 8192-t } share (c_k, s_k).
//   In-place packed FFMA2 mode-sum (even/odd k), scalar combine + A&S-3 gelu.
// grid (9 chunks, 64 b), 256 threads.
// ---------------------------------------------------------------------------
__global__ void __launch_bounds__(256) fno_main(
    const float* __restrict__ b1,
    const float* __restrict__ w2,
    const float* __restrict__ b2,
    float* __restrict__ out)
{
    __shared__ float4 Rs[NH * 8];      // 16 KB, (P,Q) pairs per mode
    __shared__ float  b1s[NH], w2s[NH];

    const int b = blockIdx.y;
    const float4* Rg = g_R + b * NH * 8;
    for (int i = threadIdx.x; i < NH * 8; i += 256) Rs[i] = Rg[i];
    if (threadIdx.x < NH) {
        b1s[threadIdx.x] = b1[threadIdx.x];
        w2s[threadIdx.x] = w2[threadIdx.x];
    }
    __syncthreads();

    const int t = blockIdx.x * 256 + threadIdx.x;
    if (t > 2048) return;

    // trig via one sincos + Chebyshev recurrence, packed (c,s) per mode
    float c[MODES], s[MODES];
    float ang = (float)t * 7.6699039394282067e-4f;  // 2*pi/8192
    float s1, c1;
    sincosf(ang, &s1, &c1);
    c[0] = 1.f; s[0] = 0.f;
    c[1] = c1;  s[1] = s1;
    const float t2 = 2.f * c1;
#pragma unroll
    for (int k = 2; k < MODES; k++) {
        c[k] = fmaf(t2, c[k - 1], -c[k - 2]);
        s[k] = fmaf(t2, s[k - 1], -s[k - 2]);
    }
    u64 cs[MODES];
#pragma unroll
    for (int k = 0; k < MODES; k++) cs[k] = pk2(c[k], s[k]);

    float acc1 = 0.f, acc2 = 0.f, acc3 = 0.f, acc4 = 0.f;
#pragma unroll 2
    for (int j = 0; j < NH; j++) {
        const ulonglong2* rj = (const ulonglong2*)(Rs + j * 8);
        u64 e = 0ULL, o = 0ULL;        // (Sum P*c, Sum Q*s) even / odd modes
#pragma unroll
        for (int kp = 0; kp < 8; kp++) {
            ulonglong2 rr = rj[kp];    // ld.shared.v2.u64 (broadcast)
            ffma2i(e, rr.x, cs[2 * kp]);
            ffma2i(o, rr.y, cs[2 * kp + 1]);
        }
        float ePc, eQs, oPc, oQs;
        upk2(e, ePc, eQs);
        upk2(o, oPc, oQs);
        const float bb = b1s[j];
        float S1 = ePc + eQs, S2 = oPc + oQs;
        float S3 = ePc - eQs, S4 = oPc - oQs;
        float hA = bb + S1;
        float hB = bb + S3;
        float h1 = hA + S2;   // pos t
        float h3 = hA - S2;   // pos 4096+t
        float h4 = hB + S4;   // pos 8192-t
        float h2 = hB - S4;   // pos 4096-t
        float g1 = gelu1(h1);
        float g2 = gelu1(h2);
        float g3 = gelu1(h3);
        float g4 = gelu1(h4);
        const float wj = w2s[j];
        acc1 = fmaf(g1, wj, acc1);
        acc2 = fmaf(g2, wj, acc2);
        acc3 = fmaf(g3, wj, acc3);
        acc4 = fmaf(g4, wj, acc4);
    }
    const float bias2 = b2[0];
    float* ob = out + b * LOUT;
    ob[t] = acc1 + bias2;                                   // 0..2048
    if (t > 0 && t < 2048) ob[4096 - t] = acc2 + bias2;     // 2049..4095
    ob[4096 + t] = acc3 + bias2;                            // 4096..6144
    if (t > 2 && t < 2048) ob[8192 - t] = acc4 + bias2;     // 6145..8189
}

// ---------------------------------------------------------------------------
extern "C" void kernel_launch(void* const* d_in, const int* in_sizes, int n_in,
                              void* d_out, int out_size)
{
    // inputs: token, [x_len], w_dec, b_dec, w1, b1, w2, b2
    const float* token = (const float*)d_in[0];
    int wi = (in_sizes[1] < 100) ? 2 : 1;   // skip x_len scalar if present
    const float* wdec = (const float*)d_in[wi + 0];
    const float* bdec = (const float*)d_in[wi + 1];
    const float* w1   = (const float*)d_in[wi + 2];
    const float* b1   = (const float*)d_in[wi + 3];
    const float* w2   = (const float*)d_in[wi + 4];
    const float* b2   = (const float*)d_in[wi + 5];
    float* out = (float*)d_out;

    fno_decode_gemm<<<dim3(DECM / 128, KS), 128>>>(token, wdec);
    fno_reduce<<<B * DECM / 512, 256>>>(bdec);
    fno_build_R<<<dim3(B, 8), 128>>>(w1);
    fno_main<<<dim3(9, B), 256>>>(b1, w2, b2, out);
}